// round 14
// baseline (speedup 1.0000x reference)
#include <cuda_runtime.h>

// Problem constants (fixed: v, v_pred are [4, 8192, 3] fp32, N(0,1) data)
#define BATCH    4
#define NPTS     8192
#define NB       64              // bins over coordinate 0
#define NSEG     64              // segments per batch for deterministic ranking
#define SEGLEN   (NPTS/NSEG)     // 128
#define EDGE0    (-4.0f)
#define BINW     0.125f
#define INVW     8.0f
#define MAXPAIRS 4160            // >= (8192 + 64 pads)/2 per batch
#define TOTALX   (BATCH*NPTS)    // 32768
#define K4T      128             // main-kernel threads
#define K4XB     (NPTS/K4T)      // 64 blocks per batch
#define K4NB     (K4XB*BATCH)    // 256 blocks total
#define PERTHR   (TOTALX/K4T)    // 256 floats per thread in final reduce

// Scratch (allocation-free rule; ~1.2 MB total). cnt_* are zeroed at module
// load and re-zeroed by k2 after consumption -> replay-safe.
__device__ int    cnt_y[BATCH][NB][NSEG];
__device__ int    cnt_x[BATCH][NB][NSEG];
__device__ int    off_y[BATCH][NB][NSEG];
__device__ int    off_x[BATCH][NB][NSEG];
__device__ int    binPairStart[BATCH][NB];
__device__ int    binPairCnt[BATCH][NB];
__device__ float4 ysA[BATCH][MAXPAIRS];  // (x0,x1,y0,y1) per y-pair
__device__ float4 ysB[BATCH][MAXPAIRS];  // (z0,z1,w0,w1), w = |y|^2
__device__ float4 xs[BATCH][NPTS];       // sorted x points (x,y,z,unused)
__device__ float  g_minf[TOTALX];        // per-sorted-x min d^2 (fully rewritten)
__device__ unsigned g_count;             // completion counter (self-resetting)

// ---- Blackwell packed-f32x2 helpers (only FFMA2 exists packed in PTX) ----
__device__ __forceinline__ unsigned long long pack2(float lo, float hi) {
    unsigned long long r;
    asm("mov.b64 %0, {%1, %2};" : "=l"(r) : "f"(lo), "f"(hi));
    return r;
}
__device__ __forceinline__ unsigned long long ffma2(unsigned long long a,
                                                    unsigned long long b,
                                                    unsigned long long c) {
    unsigned long long d;
    asm("fma.rn.f32x2 %0, %1, %2, %3;" : "=l"(d) : "l"(a), "l"(b), "l"(c));
    return d;
}
__device__ __forceinline__ void unpack2(unsigned long long v, float& lo, float& hi) {
    asm("mov.b64 {%0, %1}, %2;" : "=f"(lo), "=f"(hi) : "l"(v));
}

__device__ __forceinline__ int binOf(float v) {
    int b = (int)((v - EDGE0) * INVW);
    return min(max(b, 0), NB - 1);
}

// K1: histogram both clouds by (batch, bin, segment). Counts are order-free.
__global__ __launch_bounds__(256)
void k1_count(const float* __restrict__ v, const float* __restrict__ vp) {
    int gid = blockIdx.x * 256 + threadIdx.x;   // 0 .. 2*TOTALX-1
    if (gid < TOTALX) {
        int bat = gid >> 13, j = gid & (NPTS - 1);
        atomicAdd(&cnt_y[bat][binOf(v[3 * gid])][j >> 7], 1);
    } else {
        int i = gid - TOTALX;
        int bat = i >> 13, j = i & (NPTS - 1);
        atomicAdd(&cnt_x[bat][binOf(vp[3 * i])][j >> 7], 1);
    }
}

// K2: prefix counts into deterministic scatter offsets; write pad sentinels;
// zero the count arrays for the next replay. One block, 256 threads = (batch,bin).
__global__ __launch_bounds__(256)
void k2_offsets() {
    __shared__ int sPad[256], sStart[256];
    int tid = threadIdx.x, bat = tid >> 6, bin = tid & 63;
    // ---- y (padded to even element count per bin) ----
    int t = 0;
    for (int s = 0; s < NSEG; s++) t += cnt_y[bat][bin][s];
    int pc = (t + 1) & ~1;
    sPad[tid] = pc;
    __syncthreads();
    if (bin == 0) {
        int run = 0;
        for (int bb = 0; bb < NB; bb++) { sStart[bat * 64 + bb] = run; run += sPad[bat * 64 + bb]; }
    }
    __syncthreads();
    int es = sStart[tid];
    binPairStart[bat][bin] = es >> 1;
    binPairCnt[bat][bin]   = pc >> 1;
    int r = es;
    for (int s = 0; s < NSEG; s++) { off_y[bat][bin][s] = r; r += cnt_y[bat][bin][s]; cnt_y[bat][bin][s] = 0; }
    if (t & 1) {  // sentinel pad: (0,0,0) with w=1e30 -> d^2 = 1e30, never wins
        int pr = (es + t) >> 1;                  // es even, t odd -> h = 1
        float* fA = (float*)&ysA[bat][0];
        float* fB = (float*)&ysB[bat][0];
        fA[4 * pr + 1] = 0.f; fA[4 * pr + 3] = 0.f;
        fB[4 * pr + 1] = 0.f; fB[4 * pr + 3] = 1e30f;
    }
    __syncthreads();
    // ---- x (no padding) ----
    int t2 = 0;
    for (int s = 0; s < NSEG; s++) t2 += cnt_x[bat][bin][s];
    sPad[tid] = t2;
    __syncthreads();
    if (bin == 0) {
        int run = 0;
        for (int bb = 0; bb < NB; bb++) { sStart[bat * 64 + bb] = run; run += sPad[bat * 64 + bb]; }
    }
    __syncthreads();
    int r2 = sStart[tid];
    for (int s = 0; s < NSEG; s++) { off_x[bat][bin][s] = r2; r2 += cnt_x[bat][bin][s]; cnt_x[bat][bin][s] = 0; }
}

// K3: deterministic scatter. Thread (bat,bin,seg) walks its 128 source indices
// in order, emitting its bin's members at exact ranks. Warp = 32 bins @ same
// seg -> all loads are warp-broadcast.
__global__ __launch_bounds__(1024)
void k3_scatter(const float* __restrict__ v, const float* __restrict__ vp) {
    int bat = blockIdx.y, sg = blockIdx.x;
    int tid = threadIdx.x;
    int bin = tid & 63, seg = sg * 16 + (tid >> 6);
    int base = seg * SEGLEN;
    float* fA = (float*)&ysA[bat][0];
    float* fB = (float*)&ysB[bat][0];
    int r = off_y[bat][bin][seg];
    for (int ii = 0; ii < SEGLEN; ii++) {
        int gi = bat * NPTS + base + ii;
        float yx = v[3 * gi], yy = v[3 * gi + 1], yz = v[3 * gi + 2];
        if (binOf(yx) == bin) {
            int pr = r >> 1, h = r & 1;
            fA[4 * pr + h]     = yx;  fA[4 * pr + 2 + h] = yy;
            fB[4 * pr + h]     = yz;  fB[4 * pr + 2 + h] = yx * yx + yy * yy + yz * yz;
            r++;
        }
    }
    float* fx = (float*)&xs[bat][0];
    int r2 = off_x[bat][bin][seg];
    for (int ii = 0; ii < SEGLEN; ii++) {
        int gi = bat * NPTS + base + ii;
        float xx = vp[3 * gi], xy = vp[3 * gi + 1], xz = vp[3 * gi + 2];
        if (binOf(xx) == bin) {
            fx[4 * r2] = xx; fx[4 * r2 + 1] = xy; fx[4 * r2 + 2] = xz;
            r2++;
        }
    }
}

// K4: main. Warp = 32 consecutive sorted x. Expanding bin walk with exact
// lower-bound skip/termination; packed FFMA2 inner loop; last block reduces.
__global__ __launch_bounds__(K4T)
void k4_main(float* __restrict__ out) {
    int bat = blockIdx.y;
    int gx  = blockIdx.x * K4T + threadIdx.x;
    int tid = threadIdx.x;

    float4 X = xs[bat][gx];
    float xx = X.x;
    unsigned long long ax2 = pack2(-2.f * X.x, -2.f * X.x);
    unsigned long long ay2 = pack2(-2.f * X.y, -2.f * X.y);
    unsigned long long az2 = pack2(-2.f * X.z, -2.f * X.z);
    float x2 = X.x * X.x + X.y * X.y + X.z * X.z;
    float mlo = 1e38f, mhi = 1e38f;

    int b0 = binOf(__shfl_sync(0xFFFFFFFFu, xx, 0));
    const ulonglong2* uA = (const ulonglong2*)&ysA[bat][0];
    const ulonglong2* uB = (const ulonglong2*)&ysB[bat][0];

    for (int k = 0; k < NB; k++) {
        #pragma unroll
        for (int side = 0; side < 2; side++) {
            if (k == 0 && side == 1) continue;
            int bb = (side == 0) ? (b0 - k) : (b0 + k);
            if (bb < 0 || bb >= NB) continue;
            // Exact interval bound (end bins are half-infinite -> clamp-safe)
            float lo = (bb == 0)      ? -1e30f : (EDGE0 + BINW * bb);
            float hi = (bb == NB - 1) ?  1e30f : (EDGE0 + BINW * (bb + 1));
            float d  = fmaxf(0.f, fmaxf(lo - xx, xx - hi));
            float mm = x2 + fminf(mlo, mhi);
            if (__all_sync(0xFFFFFFFFu, d * d - 1e-6f > mm)) continue;
            int ps = binPairStart[bat][bb];
            int pe = ps + binPairCnt[bat][bb];
            #pragma unroll 2
            for (int j = ps; j < pe; j++) {
                ulonglong2 A  = uA[j];
                ulonglong2 Bv = uB[j];
                unsigned long long t = ffma2(ax2, A.x, Bv.y);
                t = ffma2(ay2, A.y, t);
                t = ffma2(az2, Bv.x, t);
                float plo, phi;
                unpack2(t, plo, phi);
                mlo = fminf(mlo, plo);
                mhi = fminf(mhi, phi);
            }
        }
        // Termination: all remaining bins provably too far for every lane.
        float mm = x2 + fminf(mlo, mhi);
        float bl = 1e30f, br = 1e30f;
        if (b0 - k - 1 >= 0) {
            float e = EDGE0 + BINW * (b0 - k);
            float dd = fmaxf(0.f, xx - e);
            bl = dd * dd - 1e-6f;
        }
        if (b0 + k + 1 < NB) {
            float e = EDGE0 + BINW * (b0 + k + 1);
            float dd = fmaxf(0.f, e - xx);
            br = dd * dd - 1e-6f;
        }
        if (__all_sync(0xFFFFFFFFu, fminf(bl, br) > mm)) break;
    }

    g_minf[bat * NPTS + gx] = x2 + fminf(mlo, mhi);

    // Last-block fused reduction (threadFenceReduction pattern).
    __shared__ unsigned s_last;
    __threadfence();
    __syncthreads();
    if (tid == 0) s_last = (atomicAdd(&g_count, 1u) == K4NB - 1u);
    __syncthreads();
    if (s_last) {
        __shared__ float ssum[K4T];
        float acc = 0.0f;
        const float4* g4 = (const float4*)g_minf;
        #pragma unroll
        for (int q = 0; q < PERTHR / 4; q++) {
            float4 f = g4[tid * (PERTHR / 4) + q];
            acc += f.x + f.y + f.z + f.w;
        }
        ssum[tid] = acc;
        __syncthreads();
        #pragma unroll
        for (int s = K4T / 2; s > 0; s >>= 1) {
            if (tid < s) ssum[tid] += ssum[tid + s];
            __syncthreads();
        }
        if (tid == 0) {
            out[0] = ssum[0] / (float)TOTALX;
            g_count = 0;  // self-reset for next replay
        }
    }
}

extern "C" void kernel_launch(void* const* d_in, const int* in_sizes, int n_in,
                              void* d_out, int out_size) {
    const float* v  = (const float*)d_in[0];   // target y
    const float* vp = (const float*)d_in[1];   // pred   x
    float* out = (float*)d_out;

    k1_count<<<(2 * TOTALX) / 256, 256>>>(v, vp);
    k2_offsets<<<1, 256>>>();
    k3_scatter<<<dim3(4, BATCH), 1024>>>(v, vp);
    k4_main<<<dim3(K4XB, BATCH), K4T>>>(out);
}

// round 15
// speedup vs baseline: 6.1862x; 6.1862x over previous
#include <cuda_runtime.h>

// Problem constants (fixed: v, v_pred are [4, 8192, 3] fp32, N(0,1) data)
#define BATCH    4
#define NPTS     8192
#define NB       64              // bins over coordinate 0
#define EDGE0    (-4.0f)
#define BINW     0.125f
#define INVW     8.0f
#define MAXPAIRS 4160            // >= (8192 + 64 pads)/2 per batch
#define TOTALX   (BATCH*NPTS)    // 32768
#define XPB      64              // sorted x per k4 block
#define SLICES   8               // y-slices per x
#define K4T      (XPB*SLICES)    // 512 threads
#define K4NBLK   (TOTALX/XPB)    // 512 blocks
#define TS       512             // staged pairs per shared tile
#define PERTHR   (TOTALX/K4T)    // 64 floats per thread in final reduce

// ---- Scratch (allocation-free rule; zero-init at load, k2 re-zeroes) ----
__device__ int    cntY[BATCH][NB],  cntX[BATCH][NB];
__device__ int    fillY[BATCH][NB], fillX[BATCH][NB];
__device__ int    startY[BATCH][NB], startX[BATCH][NB];   // element starts
__device__ int    pairStart[BATCH][NB], pairCnt[BATCH][NB];
__device__ int    totalPairsArr[BATCH];
__device__ float4 ysA[BATCH][MAXPAIRS];  // (y0.x,y1.x,y0.y,y1.y)
__device__ float4 ysB[BATCH][MAXPAIRS];  // (y0.z,y1.z,|y0|^2,|y1|^2)
__device__ float4 xs[BATCH][NPTS];       // sorted x: (x,y,z, origIdx bits)
__device__ float  g_minf[TOTALX];        // indexed by ORIGINAL x index
__device__ unsigned g_count;

// ---- Blackwell packed-f32x2 helpers ----
__device__ __forceinline__ unsigned long long pack2(float lo, float hi) {
    unsigned long long r;
    asm("mov.b64 %0, {%1, %2};" : "=l"(r) : "f"(lo), "f"(hi));
    return r;
}
__device__ __forceinline__ unsigned long long ffma2(unsigned long long a,
                                                    unsigned long long b,
                                                    unsigned long long c) {
    unsigned long long d;
    asm("fma.rn.f32x2 %0, %1, %2, %3;" : "=l"(d) : "l"(a), "l"(b), "l"(c));
    return d;
}
__device__ __forceinline__ void unpack2(unsigned long long v, float& lo, float& hi) {
    asm("mov.b64 {%0, %1}, %2;" : "=f"(lo), "=f"(hi) : "l"(v));
}
__device__ __forceinline__ int binOf(float v) {
    int b = (int)((v - EDGE0) * INVW);
    return min(max(b, 0), NB - 1);
}

// K1: histogram both clouds by (batch, bin). Counts order-free -> deterministic.
__global__ __launch_bounds__(256)
void k1_count(const float* __restrict__ v, const float* __restrict__ vp) {
    int gid = blockIdx.x * 256 + threadIdx.x;       // 0 .. 2*TOTALX-1
    if (gid < TOTALX) {
        int bat = gid >> 13;
        atomicAdd(&cntY[bat][binOf(v[3 * gid])], 1);
    } else {
        int i = gid - TOTALX;
        int bat = i >> 13;
        atomicAdd(&cntX[bat][binOf(vp[3 * i])], 1);
    }
}

// K2: prefix sums (y padded to even per bin), sentinel pads, zero counters.
__global__ __launch_bounds__(256)
void k2_offsets() {
    __shared__ int sVal[256], sStart[256];
    int tid = threadIdx.x, bat = tid >> 6, bin = tid & 63;
    // ---- y prefix (padded even) ----
    int t = cntY[bat][bin];
    int padded = (t + 1) & ~1;
    sVal[tid] = padded;
    __syncthreads();
    if (bin == 0) {
        int run = 0;
        for (int b = 0; b < NB; b++) { sStart[bat * 64 + b] = run; run += sVal[bat * 64 + b]; }
    }
    __syncthreads();
    int es = sStart[tid];
    startY[bat][bin]    = es;
    pairStart[bat][bin] = es >> 1;
    pairCnt[bat][bin]   = padded >> 1;
    if (bin == NB - 1) totalPairsArr[bat] = (es + padded) >> 1;
    if (t & 1) {   // sentinel pad at element es+t (h==1): never wins the min
        int pr = (es + t) >> 1;
        float* fA = (float*)&ysA[bat][0];
        float* fB = (float*)&ysB[bat][0];
        fA[4 * pr + 1] = 0.f; fA[4 * pr + 3] = 0.f;
        fB[4 * pr + 1] = 0.f; fB[4 * pr + 3] = 1e30f;
    }
    __syncthreads();
    // ---- x prefix (no padding) ----
    int t2 = cntX[bat][bin];
    sVal[tid] = t2;
    __syncthreads();
    if (bin == 0) {
        int run = 0;
        for (int b = 0; b < NB; b++) { sStart[bat * 64 + b] = run; run += sVal[bat * 64 + b]; }
    }
    __syncthreads();
    startX[bat][bin] = sStart[tid];
    // zero counters for this replay's k3 and the NEXT replay's k1
    cntY[bat][bin] = 0; cntX[bat][bin] = 0;
    fillY[bat][bin] = 0; fillX[bat][bin] = 0;
}

// K3: scatter. Rank within bin via atomicAdd (order-free: min is exact and x
// results are stored by ORIGINAL index, so output stays deterministic).
__global__ __launch_bounds__(256)
void k3_scatter(const float* __restrict__ v, const float* __restrict__ vp) {
    int gid = blockIdx.x * 256 + threadIdx.x;
    if (gid < TOTALX) {
        int bat = gid >> 13;
        float yx = v[3 * gid], yy = v[3 * gid + 1], yz = v[3 * gid + 2];
        int bin = binOf(yx);
        int r = startY[bat][bin] + atomicAdd(&fillY[bat][bin], 1);
        int pr = r >> 1, h = r & 1;
        float* fA = (float*)&ysA[bat][0];
        float* fB = (float*)&ysB[bat][0];
        fA[4 * pr + h]     = yx;  fA[4 * pr + 2 + h] = yy;
        fB[4 * pr + h]     = yz;  fB[4 * pr + 2 + h] = yx * yx + yy * yy + yz * yz;
    } else {
        int i = gid - TOTALX;
        int bat = i >> 13, j = i & (NPTS - 1);
        float xx = vp[3 * i], xy = vp[3 * i + 1], xz = vp[3 * i + 2];
        int bin = binOf(xx);
        int r = startX[bat][bin] + atomicAdd(&fillX[bat][bin], 1);
        xs[bat][r] = make_float4(xx, xy, xz, __int_as_float(j));
    }
}

// K4: block = 64 consecutive sorted x * 8 slices. UB -> contiguous window ->
// shared-staged packed brute force -> per-x exact min -> fused final reduce.
__global__ __launch_bounds__(K4T)
void k4_main(float* __restrict__ out) {
    const int bat   = blockIdx.y;
    const int tid   = threadIdx.x;
    const int xlane = tid & (XPB - 1);
    const int slice = tid >> 6;              // 0..7, warp-uniform (64/slice)
    const int base  = blockIdx.x * XPB;

    __shared__ float4 sA[TS], sB[TS];
    __shared__ float  sRed[K4T];
    __shared__ unsigned s_last;

    float4 X = xs[bat][base + xlane];
    const int orig = __float_as_int(X.w);
    unsigned long long ax2 = pack2(-2.f * X.x, -2.f * X.x);
    unsigned long long ay2 = pack2(-2.f * X.y, -2.f * X.y);
    unsigned long long az2 = pack2(-2.f * X.z, -2.f * X.z);
    const float x2 = X.x * X.x + X.y * X.y + X.z * X.z;

    const ulonglong2* gA = (const ulonglong2*)&ysA[bat][0];
    const ulonglong2* gB = (const ulonglong2*)&ysB[bat][0];
    const int totP = totalPairsArr[bat];

    // Phase A: upper bound from 64 pairs (128 y) near this x's bin (never empty).
    int us = pairStart[bat][binOf(X.x)] - 16;
    us = max(0, min(us, totP - 64));
    float ub = 1e38f;
    for (int j = us + slice; j < us + 64; j += SLICES) {
        ulonglong2 A  = gA[j];
        ulonglong2 Bv = gB[j];
        unsigned long long t = ffma2(ax2, A.x, Bv.y);
        t = ffma2(ay2, A.y, t);
        t = ffma2(az2, Bv.x, t);
        float lo, hi; unpack2(t, lo, hi);
        ub = fminf(ub, fminf(lo, hi));
    }
    sRed[tid] = ub;
    __syncthreads();
    if (slice == 0) {                        // min over slices, + x^2 -> UB_x
        float m = sRed[xlane];
        #pragma unroll
        for (int s = 1; s < SLICES; s++) m = fminf(m, sRed[xlane + XPB * s]);
        sRed[xlane] = x2 + m;
    }
    __syncthreads();
    for (int s = XPB / 2; s > 0; s >>= 1) {  // max over the 64 x
        if (tid < s) sRed[tid] = fmaxf(sRed[tid], sRed[tid + s]);
        __syncthreads();
    }
    const float Rsq = sRed[0];
    __syncthreads();

    // Phase B: contiguous window over sorted y (bin-granular, margin-padded).
    const float R = sqrtf(fminf(Rsq, 1e30f)) * 1.001f + 1e-2f;
    const float xfirst = xs[bat][base].x;
    const float xlast  = xs[bat][base + XPB - 1].x;
    const int blo = binOf(xfirst - R);
    const int bhi = binOf(xlast + R);
    const int pLo = pairStart[bat][blo];
    const int pHi = pairStart[bat][bhi] + pairCnt[bat][bhi];

    float mlo = 1e38f, mhi = 1e38f;
    for (int t0 = pLo; t0 < pHi; t0 += TS) {
        const int n = min(TS, pHi - t0);
        __syncthreads();
        for (int i = tid; i < n; i += K4T) { sA[i] = ysA[bat][t0 + i]; sB[i] = ysB[bat][t0 + i]; }
        __syncthreads();
        const ulonglong2* uA = (const ulonglong2*)sA;
        const ulonglong2* uB = (const ulonglong2*)sB;
        for (int j = slice; j < n; j += SLICES) {     // warp-broadcast LDS
            ulonglong2 A  = uA[j];
            ulonglong2 Bv = uB[j];
            unsigned long long t = ffma2(ax2, A.x, Bv.y);
            t = ffma2(ay2, A.y, t);
            t = ffma2(az2, Bv.x, t);
            float lo, hi; unpack2(t, lo, hi);
            mlo = fminf(mlo, lo);
            mhi = fminf(mhi, hi);
        }
    }
    __syncthreads();
    sRed[tid] = fminf(mlo, mhi);
    __syncthreads();
    if (slice == 0) {                        // fixed-order slice merge
        float m = sRed[xlane];
        #pragma unroll
        for (int s = 1; s < SLICES; s++) m = fminf(m, sRed[xlane + XPB * s]);
        g_minf[bat * NPTS + orig] = x2 + m;  // by ORIGINAL index -> deterministic
    }

    // Fused last-block reduction (threadFenceReduction pattern).
    __threadfence();
    __syncthreads();
    if (tid == 0) s_last = (atomicAdd(&g_count, 1u) == K4NBLK - 1u);
    __syncthreads();
    if (s_last) {
        float acc = 0.0f;
        const float4* g4 = (const float4*)g_minf;
        #pragma unroll
        for (int q = 0; q < PERTHR / 4; q++) {
            float4 f = g4[tid * (PERTHR / 4) + q];
            acc += f.x + f.y + f.z + f.w;
        }
        sRed[tid] = acc;
        __syncthreads();
        #pragma unroll
        for (int s = K4T / 2; s > 0; s >>= 1) {
            if (tid < s) sRed[tid] += sRed[tid + s];
            __syncthreads();
        }
        if (tid == 0) {
            out[0] = sRed[0] / (float)TOTALX;
            g_count = 0;   // self-reset for next graph replay
        }
    }
}

extern "C" void kernel_launch(void* const* d_in, const int* in_sizes, int n_in,
                              void* d_out, int out_size) {
    const float* v  = (const float*)d_in[0];   // target y
    const float* vp = (const float*)d_in[1];   // pred   x
    float* out = (float*)d_out;

    k1_count<<<(2 * TOTALX) / 256, 256>>>(v, vp);
    k2_offsets<<<1, 256>>>();
    k3_scatter<<<(2 * TOTALX) / 256, 256>>>(v, vp);
    k4_main<<<dim3(K4NBLK / BATCH, BATCH), K4T>>>(out);
}

// round 16
// speedup vs baseline: 6.3463x; 1.0259x over previous
#include <cuda_runtime.h>

// Problem constants (fixed: v, v_pred are [4, 8192, 3] fp32, N(0,1) data)
#define BATCH    4
#define NPTS     8192
#define NB       64              // bins over coordinate 0
#define EDGE0    (-4.0f)
#define BINW     0.125f
#define INVW     8.0f
#define MAXPAIRS 4160
#define TOTALX   (BATCH*NPTS)    // 32768
#define XPB      32              // sorted x per k4 block (warp-sized)
#define SLICES   8               // slice warps
#define K4T      256             // threads per k4 block
#define K4NBLK   (TOTALX/XPB)    // 1024 blocks
#define TS       512             // staged pairs per tile
#define TSP      (TS+32)         // padded tile capacity
#define PERTHR   (TOTALX/K4T)    // 128 floats per thread in final reduce

// ---- Scratch (allocation-free; zero-init at load; k2 re-zeroes counters) ----
__device__ int    cntY[BATCH][NB],  cntX[BATCH][NB];
__device__ int    fillY[BATCH][NB], fillX[BATCH][NB];
__device__ int    startY[BATCH][NB], startX[BATCH][NB];
__device__ int    pairStart[BATCH][NB], pairCnt[BATCH][NB];
__device__ int    totalPairsArr[BATCH];
__device__ float4 ysA[BATCH][MAXPAIRS];  // (y0.x,y1.x,y0.y,y1.y)
__device__ float4 ysB[BATCH][MAXPAIRS];  // (y0.z,y1.z,|y0|^2,|y1|^2)
__device__ float4 xs[BATCH][NPTS];       // sorted x: (x,y,z, origIdx bits)
__device__ float  g_minf[TOTALX];        // indexed by ORIGINAL x index
__device__ unsigned g_count;

// ---- Blackwell packed-f32x2 helpers ----
__device__ __forceinline__ unsigned long long pack2(float lo, float hi) {
    unsigned long long r;
    asm("mov.b64 %0, {%1, %2};" : "=l"(r) : "f"(lo), "f"(hi));
    return r;
}
__device__ __forceinline__ unsigned long long ffma2(unsigned long long a,
                                                    unsigned long long b,
                                                    unsigned long long c) {
    unsigned long long d;
    asm("fma.rn.f32x2 %0, %1, %2, %3;" : "=l"(d) : "l"(a), "l"(b), "l"(c));
    return d;
}
__device__ __forceinline__ void unpack2(unsigned long long v, float& lo, float& hi) {
    asm("mov.b64 {%0, %1}, %2;" : "=f"(lo), "=f"(hi) : "l"(v));
}
__device__ __forceinline__ int binOf(float v) {
    int b = (int)((v - EDGE0) * INVW);
    return min(max(b, 0), NB - 1);
}

// K1: histogram both clouds by (batch, bin).
__global__ __launch_bounds__(256)
void k1_count(const float* __restrict__ v, const float* __restrict__ vp) {
    int gid = blockIdx.x * 256 + threadIdx.x;       // 0 .. 2*TOTALX-1
    if (gid < TOTALX) {
        int bat = gid >> 13;
        atomicAdd(&cntY[bat][binOf(v[3 * gid])], 1);
    } else {
        int i = gid - TOTALX;
        int bat = i >> 13;
        atomicAdd(&cntX[bat][binOf(vp[3 * i])], 1);
    }
}

// K2: prefix sums (y padded even per bin), sentinel pads, zero counters.
__global__ __launch_bounds__(256)
void k2_offsets() {
    __shared__ int sVal[256], sStart[256];
    int tid = threadIdx.x, bat = tid >> 6, bin = tid & 63;
    int t = cntY[bat][bin];
    int padded = (t + 1) & ~1;
    sVal[tid] = padded;
    __syncthreads();
    if (bin == 0) {
        int run = 0;
        for (int b = 0; b < NB; b++) { sStart[bat * 64 + b] = run; run += sVal[bat * 64 + b]; }
    }
    __syncthreads();
    int es = sStart[tid];
    startY[bat][bin]    = es;
    pairStart[bat][bin] = es >> 1;
    pairCnt[bat][bin]   = padded >> 1;
    if (bin == NB - 1) totalPairsArr[bat] = (es + padded) >> 1;
    if (t & 1) {   // sentinel pad: w=1e30 never wins the min
        int pr = (es + t) >> 1;
        float* fA = (float*)&ysA[bat][0];
        float* fB = (float*)&ysB[bat][0];
        fA[4 * pr + 1] = 0.f; fA[4 * pr + 3] = 0.f;
        fB[4 * pr + 1] = 0.f; fB[4 * pr + 3] = 1e30f;
    }
    __syncthreads();
    int t2 = cntX[bat][bin];
    sVal[tid] = t2;
    __syncthreads();
    if (bin == 0) {
        int run = 0;
        for (int b = 0; b < NB; b++) { sStart[bat * 64 + b] = run; run += sVal[bat * 64 + b]; }
    }
    __syncthreads();
    startX[bat][bin] = sStart[tid];
    cntY[bat][bin] = 0; cntX[bat][bin] = 0;
    fillY[bat][bin] = 0; fillX[bat][bin] = 0;
}

// K3: scatter with atomic in-bin ranking (order-free; results keyed by orig idx).
__global__ __launch_bounds__(256)
void k3_scatter(const float* __restrict__ v, const float* __restrict__ vp) {
    int gid = blockIdx.x * 256 + threadIdx.x;
    if (gid < TOTALX) {
        int bat = gid >> 13;
        float yx = v[3 * gid], yy = v[3 * gid + 1], yz = v[3 * gid + 2];
        int bin = binOf(yx);
        int r = startY[bat][bin] + atomicAdd(&fillY[bat][bin], 1);
        int pr = r >> 1, h = r & 1;
        float* fA = (float*)&ysA[bat][0];
        float* fB = (float*)&ysB[bat][0];
        fA[4 * pr + h]     = yx;  fA[4 * pr + 2 + h] = yy;
        fB[4 * pr + h]     = yz;  fB[4 * pr + 2 + h] = yx * yx + yy * yy + yz * yz;
    } else {
        int i = gid - TOTALX;
        int bat = i >> 13, j = i & (NPTS - 1);
        float xx = vp[3 * i], xy = vp[3 * i + 1], xz = vp[3 * i + 2];
        int bin = binOf(xx);
        int r = startX[bat][bin] + atomicAdd(&fillX[bat][bin], 1);
        xs[bat][r] = make_float4(xx, xy, xz, __int_as_float(j));
    }
}

// K4: block = 32 consecutive sorted x, replicated across 8 slice warps.
// Warp-uniform UB scan -> warp-group window -> shared tiles, unrolled x4 loop.
__global__ __launch_bounds__(K4T)
void k4_main(float* __restrict__ out) {
    const int bat   = blockIdx.y;
    const int tid   = threadIdx.x;
    const int xlane = tid & (XPB - 1);   // 0..31 (lane id)
    const int slice = tid >> 5;          // 0..7  (warp id)
    const int base  = blockIdx.x * XPB;

    __shared__ float4 sA[TSP], sB[TSP];
    __shared__ float  sRed[K4T];
    __shared__ float  sR[1];
    __shared__ unsigned s_last;

    float4 X = xs[bat][base + xlane];    // every warp holds the same 32 x
    const int orig = __float_as_int(X.w);
    unsigned long long ax2 = pack2(-2.f * X.x, -2.f * X.x);
    unsigned long long ay2 = pack2(-2.f * X.y, -2.f * X.y);
    unsigned long long az2 = pack2(-2.f * X.z, -2.f * X.z);
    const float x2 = X.x * X.x + X.y * X.y + X.z * X.z;

    const int totP = totalPairsArr[bat];

    // Phase A: UB from 32 pairs near lane-0's bin (warp-uniform -> broadcast).
    float ub = 1e38f;
    {
        float x0 = __shfl_sync(0xFFFFFFFFu, X.x, 0);
        int us = pairStart[bat][binOf(x0)] - 16;
        us = max(0, min(us, totP - 32));
        const ulonglong2* gA = (const ulonglong2*)&ysA[bat][0];
        const ulonglong2* gB = (const ulonglong2*)&ysB[bat][0];
        #pragma unroll
        for (int u = 0; u < 4; u++) {
            int j = us + slice * 4 + u;
            ulonglong2 A  = gA[j];
            ulonglong2 Bv = gB[j];
            unsigned long long t = ffma2(ax2, A.x, Bv.y);
            t = ffma2(ay2, A.y, t);
            t = ffma2(az2, Bv.x, t);
            float lo, hi; unpack2(t, lo, hi);
            ub = fminf(ub, fminf(lo, hi));
        }
    }
    sRed[tid] = ub;
    __syncthreads();
    if (slice == 0) {   // warp 0: per-x UB across slices, then warp max -> Rsq
        float m = sRed[xlane];
        #pragma unroll
        for (int s = 1; s < SLICES; s++) m = fminf(m, sRed[xlane + XPB * s]);
        float ubx = x2 + m;
        #pragma unroll
        for (int w = 16; w > 0; w >>= 1)
            ubx = fmaxf(ubx, __shfl_xor_sync(0xFFFFFFFFu, ubx, w));
        if (xlane == 0) sR[0] = ubx;
    }
    __syncthreads();

    // Window bounds (uniform per block; margins dwarf FP error -> exact min).
    const float R = sqrtf(fminf(sR[0], 1e30f)) * 1.001f + 1e-2f;
    const float xfirst = __shfl_sync(0xFFFFFFFFu, X.x, 0);
    const float xlast  = __shfl_sync(0xFFFFFFFFu, X.x, XPB - 1);
    const int blo = binOf(xfirst - R);
    const int bhi = binOf(xlast + R);
    const int pLo = pairStart[bat][blo];
    const int pHi = pairStart[bat][bhi] + pairCnt[bat][bhi];

    float mlo = 1e38f, mhi = 1e38f;
    for (int t0 = pLo; t0 < pHi; t0 += TS) {
        const int n = min(TS, pHi - t0);
        const int nPad = (n + 31) & ~31;
        __syncthreads();
        for (int i = tid; i < nPad; i += K4T) {
            if (i < n) { sA[i] = ysA[bat][t0 + i]; sB[i] = ysB[bat][t0 + i]; }
            else       { sA[i] = make_float4(0.f, 0.f, 0.f, 0.f);
                         sB[i] = make_float4(0.f, 0.f, 1e30f, 1e30f); }
        }
        __syncthreads();
        const ulonglong2* uA = (const ulonglong2*)sA;
        const ulonglong2* uB = (const ulonglong2*)sB;
        // Unrolled x4: 8 independent LDS.128 + 12 FFMA2 in flight per step.
        for (int j = slice * 4; j < nPad; j += SLICES * 4) {
            #pragma unroll
            for (int u = 0; u < 4; u++) {
                ulonglong2 A  = uA[j + u];
                ulonglong2 Bv = uB[j + u];
                unsigned long long t = ffma2(ax2, A.x, Bv.y);
                t = ffma2(ay2, A.y, t);
                t = ffma2(az2, Bv.x, t);
                float lo, hi; unpack2(t, lo, hi);
                mlo = fminf(mlo, lo);
                mhi = fminf(mhi, hi);
            }
        }
    }
    __syncthreads();
    sRed[tid] = fminf(mlo, mhi);
    __syncthreads();
    if (slice == 0) {   // fixed-order slice merge; store by ORIGINAL index
        float m = sRed[xlane];
        #pragma unroll
        for (int s = 1; s < SLICES; s++) m = fminf(m, sRed[xlane + XPB * s]);
        g_minf[bat * NPTS + orig] = x2 + m;
    }

    // Fused last-block reduction (threadFenceReduction pattern).
    __threadfence();
    __syncthreads();
    if (tid == 0) s_last = (atomicAdd(&g_count, 1u) == K4NBLK - 1u);
    __syncthreads();
    if (s_last) {
        float acc = 0.0f;
        const float4* g4 = (const float4*)g_minf;
        #pragma unroll
        for (int q = 0; q < PERTHR / 4; q++) {
            float4 f = g4[tid * (PERTHR / 4) + q];
            acc += f.x + f.y + f.z + f.w;
        }
        sRed[tid] = acc;
        __syncthreads();
        #pragma unroll
        for (int s = K4T / 2; s > 0; s >>= 1) {
            if (tid < s) sRed[tid] += sRed[tid + s];
            __syncthreads();
        }
        if (tid == 0) {
            out[0] = sRed[0] / (float)TOTALX;
            g_count = 0;   // self-reset for next graph replay
        }
    }
}

extern "C" void kernel_launch(void* const* d_in, const int* in_sizes, int n_in,
                              void* d_out, int out_size) {
    const float* v  = (const float*)d_in[0];   // target y
    const float* vp = (const float*)d_in[1];   // pred   x
    float* out = (float*)d_out;

    k1_count<<<(2 * TOTALX) / 256, 256>>>(v, vp);
    k2_offsets<<<1, 256>>>();
    k3_scatter<<<(2 * TOTALX) / 256, 256>>>(v, vp);
    k4_main<<<dim3(NPTS / XPB, BATCH), K4T>>>(out);
}